// round 1
// baseline (speedup 1.0000x reference)
#include <cuda_runtime.h>
#include <cstdint>

// ---------------------------------------------------------------------------
// ProtoNet: out[q,c] = -(||z_q - proto_c||^2)
//   z_q   = xq @ W + b                       [Q, D]
//   proto = classmean(xs) @ W + b            [64, D]   (linearity of encoder)
//   out   = 2*z_q.proto^T - ||z_q||^2 - ||proto||^2
// Shapes: S=1024, Q=16384, F=2048, D=512, NWAY=64
// ---------------------------------------------------------------------------

#define NWAY 64

// Static scratch (no allocations allowed).
#define Q_MAX 16384
#define D_MAX 512
#define F_MAX 2048
#define S_SMEM 2048

__device__ float g_z[(size_t)Q_MAX * D_MAX];        // 32 MB
__device__ float g_cls_mean[NWAY * F_MAX];          // 512 KB
__device__ float g_proto[NWAY * D_MAX];             // 128 KB
__device__ float g_znorm[Q_MAX];                    // 64 KB
__device__ float g_pnorm[NWAY];
__device__ int   g_ys[4096];
__device__ float g_invcnt[NWAY];

// ---------------------------------------------------------------------------
// k_prep: detect int64-vs-int32 label layout, normalize labels, class counts.
// ---------------------------------------------------------------------------
__global__ void k_prep(const void* ys_raw, int S, int* ys_out, float* invcnt) {
    __shared__ int s_is32;
    __shared__ int s_cnt[NWAY];
    int tid = threadIdx.x;
    if (tid == 0) s_is32 = 0;
    if (tid < NWAY) s_cnt[tid] = 0;
    __syncthreads();

    // If int64 (values in [0,64)), every odd 32-bit word among the first S
    // words is a zero high-half. If int32, those words are random labels.
    const int* w32 = (const int*)ys_raw;
    for (int j = 1 + 2 * tid; j < S; j += 2 * blockDim.x) {
        if (w32[j] != 0) s_is32 = 1;   // benign race (all write 1)
    }
    __syncthreads();
    int is64 = !s_is32;

    const long long* w64 = (const long long*)ys_raw;
    for (int i = tid; i < S; i += blockDim.x) {
        int c = is64 ? (int)w64[i] : w32[i];
        ys_out[i] = c;
        atomicAdd(&s_cnt[c], 1);
    }
    __syncthreads();
    if (tid < NWAY) {
        int c = s_cnt[tid];
        invcnt[tid] = 1.0f / (float)(c > 0 ? c : 1);
    }
}

// ---------------------------------------------------------------------------
// k_cls_mean: per-class mean of xs in F-space.  grid = F/128, block = 128.
// Each thread owns one feature column; loops all S rows accumulating into a
// private-per-thread shared column slot -> no atomics in the hot loop.
// ---------------------------------------------------------------------------
__global__ void k_cls_mean(const float* __restrict__ xs, int S, int F,
                           const int* __restrict__ ys,
                           const float* __restrict__ invcnt,
                           float* __restrict__ cls_mean) {
    __shared__ float acc[NWAY][128];
    __shared__ int s_ys[S_SMEM];
    int tid = threadIdx.x;
    int f = blockIdx.x * 128 + tid;

    #pragma unroll
    for (int c = 0; c < NWAY; c++) acc[c][tid] = 0.0f;
    for (int i = tid; i < S && i < S_SMEM; i += blockDim.x) s_ys[i] = ys[i];
    __syncthreads();

    const int* ysp = (S <= S_SMEM) ? s_ys : ys;
    #pragma unroll 4
    for (int i = 0; i < S; i++) {
        acc[ysp[i]][tid] += xs[(size_t)i * F + f];
    }
    __syncthreads();

    #pragma unroll
    for (int c = 0; c < NWAY; c++) {
        cls_mean[(size_t)c * F + f] = acc[c][tid] * invcnt[c];
    }
}

// ---------------------------------------------------------------------------
// gemm_nn: C[M,N] = A[M,K] @ B[K,N] + bias[N]
// BM=128, BN=128, BK=8, 256 threads, 8x8 per thread, float4 everywhere.
// Handles M not a multiple of 128 (needed for M=64 proto GEMM).
// Requires: K % 8 == 0, N % 128 == 0.
// ---------------------------------------------------------------------------
#define BM 128
#define BN 128
#define BK 8
__global__ __launch_bounds__(256) void gemm_nn(
    const float* __restrict__ A, const float* __restrict__ B,
    const float* __restrict__ bias, float* __restrict__ C,
    int M, int N, int K)
{
    __shared__ float As[BK][BM];
    __shared__ float Bs[BK][BN];

    int tid = threadIdx.x;
    int rowBase = blockIdx.y * BM;
    int colBase = blockIdx.x * BN;

    // A: 128 rows x 8 cols = 256 float4
    int aRow = tid >> 1;
    int aCol = (tid & 1) * 4;
    // B: 8 rows x 128 cols = 256 float4
    int bRow = tid >> 5;
    int bCol = (tid & 31) * 4;

    int ty = tid >> 4;   // 0..15 -> row group (8 rows each)
    int tx = tid & 15;   // 0..15 -> col group (8 cols each)

    float acc[8][8];
    #pragma unroll
    for (int i = 0; i < 8; i++)
        #pragma unroll
        for (int j = 0; j < 8; j++) acc[i][j] = 0.0f;

    for (int k0 = 0; k0 < K; k0 += BK) {
        float4 a4 = make_float4(0.f, 0.f, 0.f, 0.f);
        int gRow = rowBase + aRow;
        if (gRow < M)
            a4 = *(const float4*)(A + (size_t)gRow * K + k0 + aCol);
        As[aCol + 0][aRow] = a4.x;
        As[aCol + 1][aRow] = a4.y;
        As[aCol + 2][aRow] = a4.z;
        As[aCol + 3][aRow] = a4.w;

        float4 b4 = *(const float4*)(B + (size_t)(k0 + bRow) * N + colBase + bCol);
        *(float4*)&Bs[bRow][bCol] = b4;
        __syncthreads();

        #pragma unroll
        for (int k = 0; k < BK; k++) {
            float a[8], b[8];
            *(float4*)&a[0] = *(const float4*)&As[k][ty * 8];
            *(float4*)&a[4] = *(const float4*)&As[k][ty * 8 + 4];
            *(float4*)&b[0] = *(const float4*)&Bs[k][tx * 8];
            *(float4*)&b[4] = *(const float4*)&Bs[k][tx * 8 + 4];
            #pragma unroll
            for (int i = 0; i < 8; i++)
                #pragma unroll
                for (int j = 0; j < 8; j++)
                    acc[i][j] = fmaf(a[i], b[j], acc[i][j]);
        }
        __syncthreads();
    }

    float bv[8];
    *(float4*)&bv[0] = *(const float4*)(bias + colBase + tx * 8);
    *(float4*)&bv[4] = *(const float4*)(bias + colBase + tx * 8 + 4);

    #pragma unroll
    for (int i = 0; i < 8; i++) {
        int r = rowBase + ty * 8 + i;
        if (r >= M) break;
        float4 o0 = make_float4(acc[i][0] + bv[0], acc[i][1] + bv[1],
                                acc[i][2] + bv[2], acc[i][3] + bv[3]);
        float4 o1 = make_float4(acc[i][4] + bv[4], acc[i][5] + bv[5],
                                acc[i][6] + bv[6], acc[i][7] + bv[7]);
        *(float4*)(C + (size_t)r * N + colBase + tx * 8)     = o0;
        *(float4*)(C + (size_t)r * N + colBase + tx * 8 + 4) = o1;
    }
}

// ---------------------------------------------------------------------------
// rownorm: out[m] = sum_k A[m,k]^2.  One warp per row. K % 4 == 0.
// ---------------------------------------------------------------------------
__global__ void rownorm(const float* __restrict__ A, float* __restrict__ out,
                        int M, int K) {
    int warp = (blockIdx.x * blockDim.x + threadIdx.x) >> 5;
    int lane = threadIdx.x & 31;
    if (warp >= M) return;
    const float* row = A + (size_t)warp * K;
    float s = 0.0f;
    for (int j = lane * 4; j < K; j += 32 * 4) {
        float4 v = *(const float4*)(row + j);
        s = fmaf(v.x, v.x, s);
        s = fmaf(v.y, v.y, s);
        s = fmaf(v.z, v.z, s);
        s = fmaf(v.w, v.w, s);
    }
    #pragma unroll
    for (int o = 16; o > 0; o >>= 1) s += __shfl_xor_sync(0xFFFFFFFFu, s, o);
    if (lane == 0) out[warp] = s;
}

// ---------------------------------------------------------------------------
// gemm_nt_epi: out[q,c] = 2 * dot(z[q,:], proto[c,:]) - znorm[q] - pnorm[c]
// A = z [M,K] row-major, B = proto [64,K] row-major.
// BM=128, BN=64, BK=32, 256 threads, 8x4 per thread. K % 32 == 0.
// ---------------------------------------------------------------------------
#define TBM 128
#define TBN 64
#define TBK 32
__global__ __launch_bounds__(256) void gemm_nt_epi(
    const float* __restrict__ A, const float* __restrict__ B,
    const float* __restrict__ znorm, const float* __restrict__ pnorm,
    float* __restrict__ out, int M, int K)
{
    __shared__ float As[TBK][TBM];
    __shared__ float Bs[TBK][TBN];

    int tid = threadIdx.x;
    int rowBase = blockIdx.y * TBM;

    int ty = tid >> 4;   // 0..15
    int tx = tid & 15;   // 0..15

    float acc[8][4];
    #pragma unroll
    for (int i = 0; i < 8; i++)
        #pragma unroll
        for (int j = 0; j < 4; j++) acc[i][j] = 0.0f;

    // loaders: colGroup = (tid%8)*4 covers 32 cols; rows stride 32
    int lCol = (tid & 7) * 4;
    int lRow = tid >> 3;   // 0..31

    for (int k0 = 0; k0 < K; k0 += TBK) {
        #pragma unroll
        for (int r = 0; r < 4; r++) {
            int gr = rowBase + lRow + r * 32;
            float4 a4 = *(const float4*)(A + (size_t)gr * K + k0 + lCol);
            As[lCol + 0][lRow + r * 32] = a4.x;
            As[lCol + 1][lRow + r * 32] = a4.y;
            As[lCol + 2][lRow + r * 32] = a4.z;
            As[lCol + 3][lRow + r * 32] = a4.w;
        }
        #pragma unroll
        for (int r = 0; r < 2; r++) {
            int gn = lRow + r * 32;   // 0..63
            float4 b4 = *(const float4*)(B + (size_t)gn * K + k0 + lCol);
            Bs[lCol + 0][gn] = b4.x;
            Bs[lCol + 1][gn] = b4.y;
            Bs[lCol + 2][gn] = b4.z;
            Bs[lCol + 3][gn] = b4.w;
        }
        __syncthreads();

        #pragma unroll
        for (int k = 0; k < TBK; k++) {
            float a[8], b[4];
            *(float4*)&a[0] = *(const float4*)&As[k][ty * 8];
            *(float4*)&a[4] = *(const float4*)&As[k][ty * 8 + 4];
            *(float4*)&b[0] = *(const float4*)&Bs[k][tx * 4];
            #pragma unroll
            for (int i = 0; i < 8; i++)
                #pragma unroll
                for (int j = 0; j < 4; j++)
                    acc[i][j] = fmaf(a[i], b[j], acc[i][j]);
        }
        __syncthreads();
    }

    float pn[4];
    *(float4*)&pn[0] = *(const float4*)(pnorm + tx * 4);

    #pragma unroll
    for (int i = 0; i < 8; i++) {
        int r = rowBase + ty * 8 + i;
        if (r >= M) break;
        float zn = znorm[r];
        float4 o;
        o.x = 2.0f * acc[i][0] - zn - pn[0];
        o.y = 2.0f * acc[i][1] - zn - pn[1];
        o.z = 2.0f * acc[i][2] - zn - pn[2];
        o.w = 2.0f * acc[i][3] - zn - pn[3];
        *(float4*)(out + (size_t)r * NWAY + tx * 4) = o;
    }
}

// ---------------------------------------------------------------------------
// Host launcher
// ---------------------------------------------------------------------------
extern "C" void kernel_launch(void* const* d_in, const int* in_sizes, int n_in,
                              void* d_out, int out_size) {
    const float* xs = (const float*)d_in[0];
    const void*  ys = d_in[1];
    const float* xq = (const float*)d_in[2];
    const float* W  = (const float*)d_in[3];
    const float* b  = (const float*)d_in[4];

    int S = in_sizes[1];
    int F = in_sizes[0] / S;
    int D = in_sizes[4];
    int Q = in_sizes[2] / F;

    float *p_z, *p_cls, *p_proto, *p_znorm, *p_pnorm, *p_invcnt;
    int *p_ys;
    cudaGetSymbolAddress((void**)&p_z, g_z);
    cudaGetSymbolAddress((void**)&p_cls, g_cls_mean);
    cudaGetSymbolAddress((void**)&p_proto, g_proto);
    cudaGetSymbolAddress((void**)&p_znorm, g_znorm);
    cudaGetSymbolAddress((void**)&p_pnorm, g_pnorm);
    cudaGetSymbolAddress((void**)&p_invcnt, g_invcnt);
    cudaGetSymbolAddress((void**)&p_ys, g_ys);

    // 1. labels + counts
    k_prep<<<1, 256>>>(ys, S, p_ys, p_invcnt);

    // 2. class means in F-space
    k_cls_mean<<<F / 128, 128>>>(xs, S, F, p_ys, p_invcnt, p_cls);

    // 3. prototypes in D-space: proto = cls_mean @ W + b   [64, D]
    {
        dim3 grid(D / BN, (NWAY + BM - 1) / BM);
        gemm_nn<<<grid, 256>>>(p_cls, W, b, p_proto, NWAY, D, F);
    }

    // 4. big GEMM: z = xq @ W + b   [Q, D]
    {
        dim3 grid(D / BN, (Q + BM - 1) / BM);
        gemm_nn<<<grid, 256>>>(xq, W, b, p_z, Q, D, F);
    }

    // 5. row norms
    rownorm<<<(Q + 7) / 8, 256>>>(p_z, p_znorm, Q, D);
    rownorm<<<(NWAY + 7) / 8, 256>>>(p_proto, p_pnorm, NWAY, D);

    // 6. fused cross-term + epilogue -> output
    {
        dim3 grid(1, (Q + TBM - 1) / TBM);
        gemm_nt_epi<<<grid, 256>>>(p_z, p_proto, p_znorm, p_pnorm,
                                   (float*)d_out, Q, D);
    }
}

// round 2
// speedup vs baseline: 1.0090x; 1.0090x over previous
#include <cuda_runtime.h>
#include <cstdint>

// ---------------------------------------------------------------------------
// ProtoNet: out[q,c] = -(||z_q - proto_c||^2)
//   z_q   = xq @ W + b                       [Q, D]
//   proto = classmean(xs) @ W + b            [64, D]   (linearity of encoder)
//   out   = 2*z_q.proto^T - ||z_q||^2 - ||proto||^2
// Shapes: S=1024, Q=16384, F=2048, D=512, NWAY=64
// ---------------------------------------------------------------------------

#define NWAY 64

// Static scratch (no allocations allowed).
#define Q_MAX 16384
#define D_MAX 512
#define F_MAX 2048
#define S_SMEM 2048

__device__ float g_z[(size_t)Q_MAX * D_MAX];        // 32 MB
__device__ float g_cls_mean[NWAY * F_MAX];          // 512 KB
__device__ float g_proto[NWAY * D_MAX];             // 128 KB
__device__ float g_znorm[Q_MAX];                    // 64 KB
__device__ float g_pnorm[NWAY];
__device__ int   g_ys[4096];
__device__ float g_invcnt[NWAY];

// ---------------------------------------------------------------------------
// k_prep: detect int64-vs-int32 label layout, normalize labels, class counts.
// ---------------------------------------------------------------------------
__global__ void k_prep(const void* ys_raw, int S, int* ys_out, float* invcnt) {
    __shared__ int s_is32;
    __shared__ int s_cnt[NWAY];
    int tid = threadIdx.x;
    if (tid == 0) s_is32 = 0;
    if (tid < NWAY) s_cnt[tid] = 0;
    __syncthreads();

    // If int64 (values in [0,64)), every odd 32-bit word among the first S
    // words is a zero high-half. If int32, those words are random labels.
    const int* w32 = (const int*)ys_raw;
    for (int j = 1 + 2 * tid; j < S; j += 2 * blockDim.x) {
        if (w32[j] != 0) s_is32 = 1;   // benign race (all write 1)
    }
    __syncthreads();
    int is64 = !s_is32;

    const long long* w64 = (const long long*)ys_raw;
    for (int i = tid; i < S; i += blockDim.x) {
        int c = is64 ? (int)w64[i] : w32[i];
        ys_out[i] = c;
        atomicAdd(&s_cnt[c], 1);
    }
    __syncthreads();
    if (tid < NWAY) {
        int c = s_cnt[tid];
        invcnt[tid] = 1.0f / (float)(c > 0 ? c : 1);
    }
}

// ---------------------------------------------------------------------------
// k_cls_mean: per-class mean of xs in F-space.  grid = F/128, block = 128.
// Each thread owns one feature column; loops all S rows accumulating into a
// private-per-thread shared column slot -> no atomics in the hot loop.
// ---------------------------------------------------------------------------
__global__ void k_cls_mean(const float* __restrict__ xs, int S, int F,
                           const int* __restrict__ ys,
                           const float* __restrict__ invcnt,
                           float* __restrict__ cls_mean) {
    __shared__ float acc[NWAY][128];
    __shared__ int s_ys[S_SMEM];
    int tid = threadIdx.x;
    int f = blockIdx.x * 128 + tid;

    #pragma unroll
    for (int c = 0; c < NWAY; c++) acc[c][tid] = 0.0f;
    for (int i = tid; i < S && i < S_SMEM; i += blockDim.x) s_ys[i] = ys[i];
    __syncthreads();

    const int* ysp = (S <= S_SMEM) ? s_ys : ys;
    #pragma unroll 4
    for (int i = 0; i < S; i++) {
        acc[ysp[i]][tid] += xs[(size_t)i * F + f];
    }
    __syncthreads();

    #pragma unroll
    for (int c = 0; c < NWAY; c++) {
        cls_mean[(size_t)c * F + f] = acc[c][tid] * invcnt[c];
    }
}

// ---------------------------------------------------------------------------
// gemm_nn: C[M,N] = A[M,K] @ B[K,N] + bias[N]
// BM=128, BN=128, BK=8, 256 threads, 8x8 per thread, float4 everywhere.
// Handles M not a multiple of 128 (needed for M=64 proto GEMM).
// Requires: K % 8 == 0, N % 128 == 0.
// ---------------------------------------------------------------------------
#define BM 128
#define BN 128
#define BK 8
__global__ __launch_bounds__(256) void gemm_nn(
    const float* __restrict__ A, const float* __restrict__ B,
    const float* __restrict__ bias, float* __restrict__ C,
    int M, int N, int K)
{
    __shared__ float As[BK][BM];
    __shared__ float Bs[BK][BN];

    int tid = threadIdx.x;
    int rowBase = blockIdx.y * BM;
    int colBase = blockIdx.x * BN;

    // A: 128 rows x 8 cols = 256 float4
    int aRow = tid >> 1;
    int aCol = (tid & 1) * 4;
    // B: 8 rows x 128 cols = 256 float4
    int bRow = tid >> 5;
    int bCol = (tid & 31) * 4;

    int ty = tid >> 4;   // 0..15 -> row group (8 rows each)
    int tx = tid & 15;   // 0..15 -> col group (8 cols each)

    float acc[8][8];
    #pragma unroll
    for (int i = 0; i < 8; i++)
        #pragma unroll
        for (int j = 0; j < 8; j++) acc[i][j] = 0.0f;

    for (int k0 = 0; k0 < K; k0 += BK) {
        float4 a4 = make_float4(0.f, 0.f, 0.f, 0.f);
        int gRow = rowBase + aRow;
        if (gRow < M)
            a4 = *(const float4*)(A + (size_t)gRow * K + k0 + aCol);
        As[aCol + 0][aRow] = a4.x;
        As[aCol + 1][aRow] = a4.y;
        As[aCol + 2][aRow] = a4.z;
        As[aCol + 3][aRow] = a4.w;

        float4 b4 = *(const float4*)(B + (size_t)(k0 + bRow) * N + colBase + bCol);
        *(float4*)&Bs[bRow][bCol] = b4;
        __syncthreads();

        #pragma unroll
        for (int k = 0; k < BK; k++) {
            float a[8], b[8];
            *(float4*)&a[0] = *(const float4*)&As[k][ty * 8];
            *(float4*)&a[4] = *(const float4*)&As[k][ty * 8 + 4];
            *(float4*)&b[0] = *(const float4*)&Bs[k][tx * 8];
            *(float4*)&b[4] = *(const float4*)&Bs[k][tx * 8 + 4];
            #pragma unroll
            for (int i = 0; i < 8; i++)
                #pragma unroll
                for (int j = 0; j < 8; j++)
                    acc[i][j] = fmaf(a[i], b[j], acc[i][j]);
        }
        __syncthreads();
    }

    float bv[8];
    *(float4*)&bv[0] = *(const float4*)(bias + colBase + tx * 8);
    *(float4*)&bv[4] = *(const float4*)(bias + colBase + tx * 8 + 4);

    #pragma unroll
    for (int i = 0; i < 8; i++) {
        int r = rowBase + ty * 8 + i;
        if (r >= M) break;
        float4 o0 = make_float4(acc[i][0] + bv[0], acc[i][1] + bv[1],
                                acc[i][2] + bv[2], acc[i][3] + bv[3]);
        float4 o1 = make_float4(acc[i][4] + bv[4], acc[i][5] + bv[5],
                                acc[i][6] + bv[6], acc[i][7] + bv[7]);
        *(float4*)(C + (size_t)r * N + colBase + tx * 8)     = o0;
        *(float4*)(C + (size_t)r * N + colBase + tx * 8 + 4) = o1;
    }
}

// ---------------------------------------------------------------------------
// rownorm: out[m] = sum_k A[m,k]^2.  One warp per row. K % 4 == 0.
// ---------------------------------------------------------------------------
__global__ void rownorm(const float* __restrict__ A, float* __restrict__ out,
                        int M, int K) {
    int warp = (blockIdx.x * blockDim.x + threadIdx.x) >> 5;
    int lane = threadIdx.x & 31;
    if (warp >= M) return;
    const float* row = A + (size_t)warp * K;
    float s = 0.0f;
    for (int j = lane * 4; j < K; j += 32 * 4) {
        float4 v = *(const float4*)(row + j);
        s = fmaf(v.x, v.x, s);
        s = fmaf(v.y, v.y, s);
        s = fmaf(v.z, v.z, s);
        s = fmaf(v.w, v.w, s);
    }
    #pragma unroll
    for (int o = 16; o > 0; o >>= 1) s += __shfl_xor_sync(0xFFFFFFFFu, s, o);
    if (lane == 0) out[warp] = s;
}

// ---------------------------------------------------------------------------
// gemm_nt_epi: out[q,c] = 2 * dot(z[q,:], proto[c,:]) - znorm[q] - pnorm[c]
// A = z [M,K] row-major, B = proto [64,K] row-major.
// BM=128, BN=64, BK=32, 256 threads, 8x4 per thread. K % 32 == 0.
// ---------------------------------------------------------------------------
#define TBM 128
#define TBN 64
#define TBK 32
__global__ __launch_bounds__(256) void gemm_nt_epi(
    const float* __restrict__ A, const float* __restrict__ B,
    const float* __restrict__ znorm, const float* __restrict__ pnorm,
    float* __restrict__ out, int M, int K)
{
    __shared__ float As[TBK][TBM];
    __shared__ float Bs[TBK][TBN];

    int tid = threadIdx.x;
    int rowBase = blockIdx.y * TBM;

    int ty = tid >> 4;   // 0..15
    int tx = tid & 15;   // 0..15

    float acc[8][4];
    #pragma unroll
    for (int i = 0; i < 8; i++)
        #pragma unroll
        for (int j = 0; j < 4; j++) acc[i][j] = 0.0f;

    // loaders: colGroup = (tid%8)*4 covers 32 cols; rows stride 32
    int lCol = (tid & 7) * 4;
    int lRow = tid >> 3;   // 0..31

    for (int k0 = 0; k0 < K; k0 += TBK) {
        #pragma unroll
        for (int r = 0; r < 4; r++) {
            int gr = rowBase + lRow + r * 32;
            float4 a4 = *(const float4*)(A + (size_t)gr * K + k0 + lCol);
            As[lCol + 0][lRow + r * 32] = a4.x;
            As[lCol + 1][lRow + r * 32] = a4.y;
            As[lCol + 2][lRow + r * 32] = a4.z;
            As[lCol + 3][lRow + r * 32] = a4.w;
        }
        #pragma unroll
        for (int r = 0; r < 2; r++) {
            int gn = lRow + r * 32;   // 0..63
            float4 b4 = *(const float4*)(B + (size_t)gn * K + k0 + lCol);
            Bs[lCol + 0][gn] = b4.x;
            Bs[lCol + 1][gn] = b4.y;
            Bs[lCol + 2][gn] = b4.z;
            Bs[lCol + 3][gn] = b4.w;
        }
        __syncthreads();

        #pragma unroll
        for (int k = 0; k < TBK; k++) {
            float a[8], b[4];
            *(float4*)&a[0] = *(const float4*)&As[k][ty * 8];
            *(float4*)&a[4] = *(const float4*)&As[k][ty * 8 + 4];
            *(float4*)&b[0] = *(const float4*)&Bs[k][tx * 4];
            #pragma unroll
            for (int i = 0; i < 8; i++)
                #pragma unroll
                for (int j = 0; j < 4; j++)
                    acc[i][j] = fmaf(a[i], b[j], acc[i][j]);
        }
        __syncthreads();
    }

    float pn[4];
    *(float4*)&pn[0] = *(const float4*)(pnorm + tx * 4);

    #pragma unroll
    for (int i = 0; i < 8; i++) {
        int r = rowBase + ty * 8 + i;
        if (r >= M) break;
        float zn = znorm[r];
        float4 o;
        o.x = 2.0f * acc[i][0] - zn - pn[0];
        o.y = 2.0f * acc[i][1] - zn - pn[1];
        o.z = 2.0f * acc[i][2] - zn - pn[2];
        o.w = 2.0f * acc[i][3] - zn - pn[3];
        *(float4*)(out + (size_t)r * NWAY + tx * 4) = o;
    }
}

// ---------------------------------------------------------------------------
// Host launcher
// ---------------------------------------------------------------------------
extern "C" void kernel_launch(void* const* d_in, const int* in_sizes, int n_in,
                              void* d_out, int out_size) {
    const float* xs = (const float*)d_in[0];
    const void*  ys = d_in[1];
    const float* xq = (const float*)d_in[2];
    const float* W  = (const float*)d_in[3];
    const float* b  = (const float*)d_in[4];

    int S = in_sizes[1];
    int F = in_sizes[0] / S;
    int D = in_sizes[4];
    int Q = in_sizes[2] / F;

    float *p_z, *p_cls, *p_proto, *p_znorm, *p_pnorm, *p_invcnt;
    int *p_ys;
    cudaGetSymbolAddress((void**)&p_z, g_z);
    cudaGetSymbolAddress((void**)&p_cls, g_cls_mean);
    cudaGetSymbolAddress((void**)&p_proto, g_proto);
    cudaGetSymbolAddress((void**)&p_znorm, g_znorm);
    cudaGetSymbolAddress((void**)&p_pnorm, g_pnorm);
    cudaGetSymbolAddress((void**)&p_invcnt, g_invcnt);
    cudaGetSymbolAddress((void**)&p_ys, g_ys);

    // 1. labels + counts
    k_prep<<<1, 256>>>(ys, S, p_ys, p_invcnt);

    // 2. class means in F-space
    k_cls_mean<<<F / 128, 128>>>(xs, S, F, p_ys, p_invcnt, p_cls);

    // 3. prototypes in D-space: proto = cls_mean @ W + b   [64, D]
    {
        dim3 grid(D / BN, (NWAY + BM - 1) / BM);
        gemm_nn<<<grid, 256>>>(p_cls, W, b, p_proto, NWAY, D, F);
    }

    // 4. big GEMM: z = xq @ W + b   [Q, D]
    {
        dim3 grid(D / BN, (Q + BM - 1) / BM);
        gemm_nn<<<grid, 256>>>(xq, W, b, p_z, Q, D, F);
    }

    // 5. row norms
    rownorm<<<(Q + 7) / 8, 256>>>(p_z, p_znorm, Q, D);
    rownorm<<<(NWAY + 7) / 8, 256>>>(p_proto, p_pnorm, NWAY, D);

    // 6. fused cross-term + epilogue -> output
    {
        dim3 grid(1, (Q + TBM - 1) / TBM);
        gemm_nt_epi<<<grid, 256>>>(p_z, p_proto, p_znorm, p_pnorm,
                                   (float*)d_out, Q, D);
    }
}